// round 16
// baseline (speedup 1.0000x reference)
#include <cuda_runtime.h>
#include <cuda_bf16.h>
#include <cstdint>

static constexpr int Bsz = 32;
static constexpr int C   = 256;
static constexpr int Nn  = 4096;
static constexpr int S   = 64;
static constexpr int CD  = 128;
static constexpr float EPS = 1e-5f;
static constexpr int KSPLIT = 4;

// ---------------- scratch ----------------
__device__ float g_rowsum[CD];
__device__ float g_bias  [CD];
__device__ __nv_bfloat16 g_wp_hi[CD * C], g_wp_lo[CD * C];
__device__ float g_bcdt[(size_t)Bsz * CD * Nn];
__device__ float g_cv  [(size_t)Bsz * CD * Nn];
__device__ __nv_bfloat16 g_ab_hi[(size_t)Bsz * S * Nn], g_ab_lo[(size_t)Bsz * S * Nn];
__device__ float g_hpart[(size_t)KSPLIT * Bsz * C * S];
__device__ float g_h2  [(size_t)Bsz * C * S];

// ---------------- helpers ----------------
#define SWZ(o)   ((o) ^ (((o) >> 3) & 0x70))
#define SWZ64(o) ((o) ^ (((o) >> 3) & 0x30))

__device__ __forceinline__ uint32_t smem_u32(const void* p) {
    uint32_t a;
    asm("{ .reg .u64 t; cvta.to.shared.u64 t, %1; cvt.u32.u64 %0, t; }" : "=r"(a) : "l"(p));
    return a;
}
__device__ __forceinline__ void ldmx4(uint32_t* r, uint32_t addr) {
    asm volatile("ldmatrix.sync.aligned.m8n8.x4.shared.b16 {%0,%1,%2,%3}, [%4];"
        : "=r"(r[0]), "=r"(r[1]), "=r"(r[2]), "=r"(r[3]) : "r"(addr));
}
__device__ __forceinline__ void ldmx4t(uint32_t* r, uint32_t addr) {
    asm volatile("ldmatrix.sync.aligned.m8n8.x4.trans.shared.b16 {%0,%1,%2,%3}, [%4];"
        : "=r"(r[0]), "=r"(r[1]), "=r"(r[2]), "=r"(r[3]) : "r"(addr));
}
__device__ __forceinline__ void mma16816(float* d, const uint32_t* a, const uint32_t* b) {
    asm volatile("mma.sync.aligned.m16n8k16.row.col.f32.bf16.bf16.f32 "
        "{%0,%1,%2,%3}, {%4,%5,%6,%7}, {%8,%9}, {%0,%1,%2,%3};"
        : "+f"(d[0]), "+f"(d[1]), "+f"(d[2]), "+f"(d[3])
        : "r"(a[0]), "r"(a[1]), "r"(a[2]), "r"(a[3]), "r"(b[0]), "r"(b[1]));
}
__device__ __forceinline__ uint32_t ldm_addr(uint32_t base, int rowbase, int lane, int kByte) {
    int o = (rowbase + (lane & 15)) * 128 + kByte + ((lane >> 4) * 16);
    return base + SWZ(o);
}
__device__ __forceinline__ uint32_t ldm_addr64(uint32_t base, int rowbase, int lane, int kByte) {
    int o = (rowbase + (lane & 15)) * 64 + kByte + ((lane >> 4) * 16);
    return base + SWZ64(o);
}
__device__ __forceinline__ void cp16(uint32_t dst, const void* src) {
    asm volatile("cp.async.ca.shared.global [%0], [%1], 16;" :: "r"(dst), "l"(src));
}
#define CP_COMMIT asm volatile("cp.async.commit_group;" ::: "memory")
#define CP_WAIT0  asm volatile("cp.async.wait_group 0;" ::: "memory")

__device__ __forceinline__ void stcs2(float* p, float2 v) {
    asm volatile("st.global.cs.v2.f32 [%0], {%1, %2};" :: "l"(p), "f"(v.x), "f"(v.y) : "memory");
}
__device__ __forceinline__ float4 ldcs4(const float* p) {
    float4 v;
    asm volatile("ld.global.cs.v4.f32 {%0, %1, %2, %3}, [%4];"
        : "=f"(v.x), "=f"(v.y), "=f"(v.z), "=f"(v.w) : "l"(p));
    return v;
}
__device__ __forceinline__ float2 ldcs2(const float* p) {
    float2 v;
    asm volatile("ld.global.cs.v2.f32 {%0, %1}, [%2];"
        : "=f"(v.x), "=f"(v.y) : "l"(p));
    return v;
}

__device__ __forceinline__ uint32_t pk(__nv_bfloat16 a, __nv_bfloat16 b) {
    return (uint32_t)__bfloat16_as_ushort(a) | ((uint32_t)__bfloat16_as_ushort(b) << 16);
}
__device__ __forceinline__ void split_sc(float x, __nv_bfloat16& h, __nv_bfloat16& l) {
    h = __float2bfloat16(x);
    l = __float2bfloat16(x - __bfloat162float(h));
}
__device__ __forceinline__ void split_f4(float4 v, uint2& hi, uint2& lo) {
    __nv_bfloat16 hx, hy, hz, hw, lx, ly, lz, lw;
    split_sc(v.x, hx, lx); split_sc(v.y, hy, ly);
    split_sc(v.z, hz, lz); split_sc(v.w, hw, lw);
    hi.x = pk(hx, hy); hi.y = pk(hz, hw);
    lo.x = pk(lx, ly); lo.y = pk(lz, lw);
}

// ---------------- K0: fold LN into proj weights ----------------
__global__ void prep_w_k(const float* __restrict__ w_bcdt,
                         const float* __restrict__ ln_w,
                         const float* __restrict__ ln_b) {
    int o = blockIdx.x, c = threadIdx.x;
    float w  = w_bcdt[o * C + c];
    float wp = w * ln_w[c];
    __nv_bfloat16 h, l; split_sc(wp, h, l);
    g_wp_hi[o * C + c] = h;
    g_wp_lo[o * C + c] = l;
    __shared__ float s1[256], s2[256];
    s1[c] = wp;
    s2[c] = w * ln_b[c];
    __syncthreads();
    for (int st = 128; st > 0; st >>= 1) {
        if (c < st) { s1[c] += s1[c + st]; s2[c] += s2[c + st]; }
        __syncthreads();
    }
    if (c == 0) { g_rowsum[o] = s1[0]; g_bias[o] = s2[0]; }
}

// ---------------- GEMM1: D[cd128][pix128] = Wp * x, K=256 in 8 K=32 panels ----------------
__global__ __launch_bounds__(256, 2) void gemm1_mma(const float* __restrict__ x) {
    extern __shared__ char sm[];
    __shared__ float sm_mean[128], sm_inv[128];
    uint32_t sb = smem_u32(sm);
    const uint32_t OA = 0, OB = 32768;
    int tid = threadIdx.x, wid = tid >> 5, lane = tid & 31;
    int b = blockIdx.y, n0 = blockIdx.x * 128;
    int wm = wid & 1, wn = wid >> 1;
    const float* xg = x + (size_t)b * C * Nn;
    float acc[4][4][4] = {};
    float4 xr[4];
    float sacc[4] = {}, sqacc[4] = {};

    auto issueA = [&](int p, int buf) {
        uint32_t da = sb + OA + buf * 16384;
#pragma unroll
        for (int i = 0; i < 2; i++) {
            int idx = tid + i * 256;
            int cd = idx >> 2, k8 = idx & 3;
            uint32_t off = SWZ64((uint32_t)(cd * 64 + k8 * 16));
            cp16(da + off,        g_wp_hi + cd * 256 + p * 32 + k8 * 8);
            cp16(da + 8192 + off, g_wp_lo + cd * 256 + p * 32 + k8 * 8);
        }
    };
    auto loadX = [&](int p) {
#pragma unroll
        for (int i = 0; i < 4; i++) {
            int idx = tid + i * 256;
            int c = idx >> 5, pix4 = idx & 31;
            float4 v = *(const float4*)(xg + (size_t)(p * 32 + c) * Nn + n0 + pix4 * 4);
            xr[i] = v;
            sacc[0] += v.x; sqacc[0] = fmaf(v.x, v.x, sqacc[0]);
            sacc[1] += v.y; sqacc[1] = fmaf(v.y, v.y, sqacc[1]);
            sacc[2] += v.z; sqacc[2] = fmaf(v.z, v.z, sqacc[2]);
            sacc[3] += v.w; sqacc[3] = fmaf(v.w, v.w, sqacc[3]);
        }
    };
    auto storeX = [&](int buf) {
        char* db = sm + OB + buf * 16384;
#pragma unroll
        for (int i = 0; i < 4; i++) {
            int idx = tid + i * 256;
            int c = idx >> 5, pix4 = idx & 31;
            uint2 hi, lo; split_f4(xr[i], hi, lo);
            uint32_t off = (uint32_t)((pix4 >> 4) * 4096) + SWZ((uint32_t)(c * 128 + (pix4 & 15) * 8));
            *(uint2*)(db + off)        = hi;
            *(uint2*)(db + 8192 + off) = lo;
        }
    };
    auto compute = [&](int buf) {
        uint32_t aB = sb + OA + buf * 16384;
        uint32_t bB = sb + OB + buf * 16384 + (uint32_t)((wn >> 1) * 4096);
        int pb2 = (wn & 1) * 64;
#pragma unroll
        for (int kk = 0; kk < 2; kk++) {
            uint32_t ah[4][4], al[4][4], bh[4][2], bl[4][2];
#pragma unroll
            for (int mt = 0; mt < 4; mt++) {
                ldmx4(ah[mt], ldm_addr64(aB,        wm * 64 + mt * 16, lane, kk * 32));
                ldmx4(al[mt], ldm_addr64(aB + 8192, wm * 64 + mt * 16, lane, kk * 32));
            }
#pragma unroll
            for (int bt = 0; bt < 2; bt++) {
                uint32_t r[4];
                ldmx4t(r, ldm_addr(bB, kk * 16, lane, pb2 + bt * 32));
                bh[bt*2][0] = r[0]; bh[bt*2][1] = r[1];
                bh[bt*2+1][0] = r[2]; bh[bt*2+1][1] = r[3];
                ldmx4t(r, ldm_addr(bB + 8192, kk * 16, lane, pb2 + bt * 32));
                bl[bt*2][0] = r[0]; bl[bt*2][1] = r[1];
                bl[bt*2+1][0] = r[2]; bl[bt*2+1][1] = r[3];
            }
#pragma unroll
            for (int mt = 0; mt < 4; mt++)
#pragma unroll
                for (int nt = 0; nt < 4; nt++) {
                    mma16816(acc[mt][nt], ah[mt], bh[nt]);
                    mma16816(acc[mt][nt], ah[mt], bl[nt]);
                    mma16816(acc[mt][nt], al[mt], bh[nt]);
                }
        }
    };

    issueA(0, 0); loadX(0); storeX(0);
    CP_COMMIT; CP_WAIT0;
    __syncthreads();
    for (int p = 0; p < 8; p++) {
        int buf = p & 1;
        if (p < 7) { issueA(p + 1, buf ^ 1); loadX(p + 1); }
        compute(buf);
        if (p < 7) {
            storeX(buf ^ 1);
            CP_COMMIT; CP_WAIT0;
            __syncthreads();
        }
    }

    // --- fused LN stats ---
    int g = lane >> 2, tig = lane & 3;
    float rs[4][2], bi[4][2];
#pragma unroll
    for (int mt = 0; mt < 4; mt++) {
        int cd0 = wm * 64 + mt * 16 + g;
        rs[mt][0] = g_rowsum[cd0];     bi[mt][0] = g_bias[cd0];
        rs[mt][1] = g_rowsum[cd0 + 8]; bi[mt][1] = g_bias[cd0 + 8];
    }
    __syncthreads();
    float* red = (float*)sm;
    {
        int r8 = tid >> 5, p4 = (tid & 31) * 4;
#pragma unroll
        for (int j = 0; j < 4; j++) {
            red[r8 * 128 + p4 + j]        = sacc[j];
            red[1024 + r8 * 128 + p4 + j] = sqacc[j];
        }
    }
    __syncthreads();
    if (tid < 128) {
        float s = 0.f, q = 0.f;
#pragma unroll
        for (int r = 0; r < 8; r++) {
            s += red[r * 128 + tid];
            q += red[1024 + r * 128 + tid];
        }
        float m = s * (1.f / 256.f);
        float var = (q - 256.f * m * m) * (1.f / 255.f);
        sm_mean[tid] = m;
        sm_inv[tid]  = rsqrtf(var + EPS);
    }
    __syncthreads();

    float* outp = g_bcdt + (size_t)b * CD * Nn + n0;
    float me[4][2], iv[4][2];
    int px[4];
#pragma unroll
    for (int nt = 0; nt < 4; nt++) {
        px[nt] = wn * 32 + nt * 8 + tig * 2;
        me[nt][0] = sm_mean[px[nt]];     iv[nt][0] = sm_inv[px[nt]];
        me[nt][1] = sm_mean[px[nt] + 1]; iv[nt][1] = sm_inv[px[nt] + 1];
    }
#pragma unroll
    for (int mt = 0; mt < 4; mt++) {
        int cd0 = wm * 64 + mt * 16 + g, cd1 = cd0 + 8;
#pragma unroll
        for (int nt = 0; nt < 4; nt++) {
            float2 v0 = make_float2(
                iv[nt][0] * (acc[mt][nt][0] - me[nt][0] * rs[mt][0]) + bi[mt][0],
                iv[nt][1] * (acc[mt][nt][1] - me[nt][1] * rs[mt][0]) + bi[mt][0]);
            float2 v1 = make_float2(
                iv[nt][0] * (acc[mt][nt][2] - me[nt][0] * rs[mt][1]) + bi[mt][1],
                iv[nt][1] * (acc[mt][nt][3] - me[nt][1] * rs[mt][1]) + bi[mt][1]);
            *(float2*)(outp + (size_t)cd0 * Nn + px[nt]) = v0;
            *(float2*)(outp + (size_t)cd1 * Nn + px[nt]) = v1;
        }
    }
}

// ---------------- grouped 3x3 conv ----------------
__global__ __launch_bounds__(256) void conv_k(const float* __restrict__ w_gw) {
    __shared__ float si[4][34][72];
    __shared__ float sw[4][4][9];
    int b = blockIdx.z, g = blockIdx.y, ys = blockIdx.x;
    int tid = threadIdx.x;
    if (tid < 144) {
        int o = tid / 36, r = tid % 36;
        sw[o][r / 9][r % 9] = w_gw[(g * 4 + o) * 36 + r];
    }
    const float* inp = g_bcdt + ((size_t)(b * CD + g * 4)) * Nn;
    int y0 = ys * 32;
    if (tid < 136) {
        int ch = tid / 34, row = tid % 34;
        si[ch][row][3]  = 0.f;
        si[ch][row][68] = 0.f;
    }
#pragma unroll
    for (int ch = 0; ch < 4; ch++) {
        for (int j = tid; j < 34 * 16; j += 256) {
            int row = j >> 4, c4 = (j & 15) * 4;
            int gy = y0 - 1 + row;
            float4 v = make_float4(0.f, 0.f, 0.f, 0.f);
            if ((unsigned)gy < 64u) v = *(const float4*)(inp + ch * Nn + gy * 64 + c4);
            *(float4*)(&si[ch][row][4 + c4]) = v;
        }
    }
    __syncthreads();
    int ly = tid >> 3, lx8 = (tid & 7) * 8;
    float acc[4][8] = {};
#pragma unroll
    for (int ch = 0; ch < 4; ch++)
#pragma unroll
        for (int ky = 0; ky < 3; ky++) {
            float r[10];
#pragma unroll
            for (int j = 0; j < 10; j++) r[j] = si[ch][ly + ky][3 + lx8 + j];
#pragma unroll
            for (int o = 0; o < 4; o++) {
                float w0 = sw[o][ch][ky*3], w1 = sw[o][ch][ky*3+1], w2 = sw[o][ch][ky*3+2];
#pragma unroll
                for (int p = 0; p < 8; p++)
                    acc[o][p] = fmaf(r[p], w0, fmaf(r[p+1], w1, fmaf(r[p+2], w2, acc[o][p])));
            }
        }
    float* op = g_cv + ((size_t)(b * CD + g * 4)) * Nn + (y0 + ly) * 64 + lx8;
#pragma unroll
    for (int o = 0; o < 4; o++) {
        *(float4*)(op + (size_t)o * Nn)     = make_float4(acc[o][0], acc[o][1], acc[o][2], acc[o][3]);
        *(float4*)(op + (size_t)o * Nn + 4) = make_float4(acc[o][4], acc[o][5], acc[o][6], acc[o][7]);
    }
}

// ---------------- softmax + AB -> bf16 planes; float4 I/O ----------------
__global__ __launch_bounds__(256) void softmax_k(const float* __restrict__ A) {
    __shared__ float shm[8], shs[8];
    int b = blockIdx.y, s = blockIdx.x;
    const float4* dt4 = (const float4*)(g_cv + ((size_t)b * CD + S + s) * Nn);
    const float4* bc4 = (const float4*)(g_cv + ((size_t)b * CD + s) * Nn);
    size_t obase = ((size_t)b * S + s) * Nn;
    int tid = threadIdx.x;
    float a = A[s];
    float v[16];
    float mx = -1e30f;
#pragma unroll
    for (int i = 0; i < 4; i++) {
        float4 d = dt4[i * 256 + tid];
        v[i*4+0] = d.x + a; v[i*4+1] = d.y + a;
        v[i*4+2] = d.z + a; v[i*4+3] = d.w + a;
        mx = fmaxf(mx, fmaxf(fmaxf(v[i*4+0], v[i*4+1]), fmaxf(v[i*4+2], v[i*4+3])));
    }
#pragma unroll
    for (int o = 16; o; o >>= 1) mx = fmaxf(mx, __shfl_xor_sync(0xffffffffu, mx, o));
    if ((tid & 31) == 0) shm[tid >> 5] = mx;
    __syncthreads();
    if (tid == 0) {
        float m = shm[0];
        for (int i = 1; i < 8; i++) m = fmaxf(m, shm[i]);
        shm[0] = m;
    }
    __syncthreads();
    mx = shm[0];
    float sum = 0.f;
#pragma unroll
    for (int i = 0; i < 16; i++) { v[i] = __expf(v[i] - mx); sum += v[i]; }
#pragma unroll
    for (int o = 16; o; o >>= 1) sum += __shfl_xor_sync(0xffffffffu, sum, o);
    if ((tid & 31) == 0) shs[tid >> 5] = sum;
    __syncthreads();
    if (tid == 0) {
        float m = 0.f;
        for (int i = 0; i < 8; i++) m += shs[i];
        shs[0] = m;
    }
    __syncthreads();
    float invs = 1.f / shs[0];
    uint2* abh = (uint2*)(g_ab_hi + obase);
    uint2* abl = (uint2*)(g_ab_lo + obase);
#pragma unroll
    for (int i = 0; i < 4; i++) {
        float4 bc = bc4[i * 256 + tid];
        float4 val = make_float4(v[i*4+0] * invs * bc.x, v[i*4+1] * invs * bc.y,
                                 v[i*4+2] * invs * bc.z, v[i*4+3] * invs * bc.w);
        uint2 hi, lo; split_f4(val, hi, lo);
        abh[i * 256 + tid] = hi;
        abl[i * 256 + tid] = lo;
    }
}

// ---------------- hgemm: K=32 panels, double buffered; split-K=4; streaming x reads ----------------
__global__ __launch_bounds__(256, 2) void hgemm_mma(const float* __restrict__ x) {
    extern __shared__ char sm[];
    uint32_t sb = smem_u32(sm);
    int tid = threadIdx.x, wid = tid >> 5, lane = tid & 31;
    int ks = blockIdx.x, mh = blockIdx.y, b = blockIdx.z;
    int wm = wid & 3, wn = wid >> 2;
    float acc[2][4][4] = {};
    const float* xg = x + (size_t)(b * 256 + mh * 128) * Nn + ks * 1024;
    size_t bbase = (size_t)(b * 64) * Nn + ks * 1024;
    float4 ar[4];

    auto issueB = [&](int p, int buf) {
        uint32_t base = sb + buf * 24576;
        int row = tid >> 2, k8 = tid & 3;
        uint32_t off = SWZ64((uint32_t)(row * 64 + k8 * 16));
        size_t src = bbase + (size_t)row * Nn + p * 32 + k8 * 8;
        cp16(base + 16384 + off, g_ab_hi + src);
        cp16(base + 20480 + off, g_ab_lo + src);
    };
    auto loadA = [&](int p) {
#pragma unroll
        for (int i = 0; i < 4; i++) {
            int idx = tid + i * 256;
            int row = idx >> 3, q = idx & 7;
            ar[i] = ldcs4(xg + (size_t)row * Nn + p * 32 + q * 4);
        }
    };
    auto storeA = [&](int buf) {
        char* da = sm + buf * 24576;
#pragma unroll
        for (int i = 0; i < 4; i++) {
            int idx = tid + i * 256;
            int row = idx >> 3, q = idx & 7;
            uint2 hi, lo; split_f4(ar[i], hi, lo);
            uint32_t off = SWZ64((uint32_t)(row * 64 + q * 8));
            *(uint2*)(da + off)        = hi;
            *(uint2*)(da + 8192 + off) = lo;
        }
    };
    auto compute = [&](int buf) {
        uint32_t aB = sb + buf * 24576;
        uint32_t bB = aB + 16384;
#pragma unroll
        for (int kk = 0; kk < 2; kk++) {
            uint32_t ah[2][4], al[2][4], bh[4][2], bl[4][2];
#pragma unroll
            for (int mt = 0; mt < 2; mt++) {
                ldmx4(ah[mt], ldm_addr64(aB,        wm * 32 + mt * 16, lane, kk * 32));
                ldmx4(al[mt], ldm_addr64(aB + 8192, wm * 32 + mt * 16, lane, kk * 32));
            }
#pragma unroll
            for (int bt = 0; bt < 2; bt++) {
                uint32_t r[4];
                ldmx4(r, ldm_addr64(bB, wn * 32 + bt * 16, lane, kk * 32));
                bh[bt*2][0] = r[0]; bh[bt*2][1] = r[2];
                bh[bt*2+1][0] = r[1]; bh[bt*2+1][1] = r[3];
                ldmx4(r, ldm_addr64(bB + 4096, wn * 32 + bt * 16, lane, kk * 32));
                bl[bt*2][0] = r[0]; bl[bt*2][1] = r[2];
                bl[bt*2+1][0] = r[1]; bl[bt*2+1][1] = r[3];
            }
#pragma unroll
            for (int mt = 0; mt < 2; mt++)
#pragma unroll
                for (int nt = 0; nt < 4; nt++) {
                    mma16816(acc[mt][nt], ah[mt], bh[nt]);
                    mma16816(acc[mt][nt], ah[mt], bl[nt]);
                    mma16816(acc[mt][nt], al[mt], bh[nt]);
                }
        }
    };

    issueB(0, 0); loadA(0); storeA(0);
    CP_COMMIT; CP_WAIT0;
    __syncthreads();
    for (int p = 0; p < 32; p++) {
        int buf = p & 1;
        if (p < 31) { issueB(p + 1, buf ^ 1); loadA(p + 1); }
        compute(buf);
        if (p < 31) {
            storeA(buf ^ 1);
            CP_COMMIT; CP_WAIT0;
            __syncthreads();
        }
    }

    int g = lane >> 2, tig = lane & 3;
    float* hp = g_hpart + (size_t)ks * (Bsz * C * S) + (size_t)(b * 256 + mh * 128) * 64;
#pragma unroll
    for (int mt = 0; mt < 2; mt++) {
        int ca = wm * 32 + mt * 16 + g;
#pragma unroll
        for (int nt = 0; nt < 4; nt++) {
            int s0 = wn * 32 + nt * 8 + tig * 2;
            *(float2*)(hp + (size_t)ca * 64 + s0)       = make_float2(acc[mt][nt][0], acc[mt][nt][1]);
            *(float2*)(hp + (size_t)(ca + 8) * 64 + s0) = make_float2(acc[mt][nt][2], acc[mt][nt][3]);
        }
    }
}

// ---------------- h2 = w_out @ h; fused split-K reduce ----------------
__global__ __launch_bounds__(256) void h2_k(const float* __restrict__ w_out) {
    __shared__ float ws[16][65];
    __shared__ float hs[16][68];
    int m0 = blockIdx.x * 64, b = blockIdx.y;
    int tid = threadIdx.x;
    int tm = tid >> 4, tn = tid & 15;
    float acc[4][4] = {};
    int lm = tid >> 2, lk4 = (tid & 3) * 4;
    int hk = tid >> 4, hs4 = (tid & 15) * 4;
    const size_t PSTRIDE = (size_t)Bsz * C * S;
    for (int k0 = 0; k0 < C; k0 += 16) {
        float4 wv = *(const float4*)(w_out + (size_t)(m0 + lm) * C + k0 + lk4);
        size_t hoff = (size_t)(b * C + k0 + hk) * S + hs4;
        float4 hv = make_float4(0.f, 0.f, 0.f, 0.f);
#pragma unroll
        for (int p = 0; p < KSPLIT; p++) {
            float4 t = *(const float4*)(g_hpart + p * PSTRIDE + hoff);
            hv.x += t.x; hv.y += t.y; hv.z += t.z; hv.w += t.w;
        }
        __syncthreads();
        ws[lk4 + 0][lm] = wv.x; ws[lk4 + 1][lm] = wv.y;
        ws[lk4 + 2][lm] = wv.z; ws[lk4 + 3][lm] = wv.w;
        hs[hk][hs4 + 0] = hv.x; hs[hk][hs4 + 1] = hv.y;
        hs[hk][hs4 + 2] = hv.z; hs[hk][hs4 + 3] = hv.w;
        __syncthreads();
#pragma unroll
        for (int k = 0; k < 16; k++) {
            float a[4], bb[4];
#pragma unroll
            for (int i = 0; i < 4; i++) a[i] = ws[k][tm * 4 + i];
#pragma unroll
            for (int j = 0; j < 4; j++) bb[j] = hs[k][tn * 4 + j];
#pragma unroll
            for (int i = 0; i < 4; i++)
#pragma unroll
                for (int j = 0; j < 4; j++) acc[i][j] = fmaf(a[i], bb[j], acc[i][j]);
        }
    }
    float* o = g_h2 + ((size_t)b * C + m0) * S;
#pragma unroll
    for (int i = 0; i < 4; i++)
#pragma unroll
        for (int j = 0; j < 4; j++)
            o[(size_t)(tm * 4 + i) * S + tn * 4 + j] = acc[i][j];
}

// ---------------- final: out[c256][pix128] = h2 @ BC + x; mh fused; streaming x/out ----------------
__global__ __launch_bounds__(256, 2) void final_mma(const float* __restrict__ x,
                                                    float* __restrict__ out) {
    extern __shared__ char sm[];
    uint32_t sb = smem_u32(sm);
    const uint32_t OAH = 0, OAL = 16384, OBH = 32768, OBL = 49152;
    int tid = threadIdx.x, wid = tid >> 5, lane = tid & 31;
    int n0 = blockIdx.x * 128, b = blockIdx.y;
    int wm = wid & 1, wn = wid >> 1;
    int g = lane >> 2, tig = lane & 3;

#pragma unroll
    for (int half = 0; half < 2; half++) {
        float4 tmp[4];
#pragma unroll
        for (int i = 0; i < 4; i++) {
            int idx = tid + (half * 4 + i) * 256;
            int s = idx >> 5, pix4 = idx & 31;
            tmp[i] = *(const float4*)(g_cv + (size_t)(b * CD + s) * Nn + n0 + pix4 * 4);
        }
#pragma unroll
        for (int i = 0; i < 4; i++) {
            int idx = tid + (half * 4 + i) * 256;
            int s = idx >> 5, pix4 = idx & 31;
            uint2 hi, lo; split_f4(tmp[i], hi, lo);
            uint32_t off = (uint32_t)((pix4 >> 4) * 8192) + SWZ((uint32_t)(s * 128 + (pix4 & 15) * 8));
            *(uint2*)(sm + OBH + off) = hi;
            *(uint2*)(sm + OBL + off) = lo;
        }
    }

    for (int mh = 0; mh < 2; mh++) {
        {
            float4 tmp[4];
#pragma unroll
            for (int half = 0; half < 2; half++) {
#pragma unroll
                for (int i = 0; i < 4; i++) {
                    int idx = tid + (half * 4 + i) * 256;
                    int row = idx >> 4, q = idx & 15;
                    tmp[i] = *(const float4*)(g_h2 + (size_t)(b * 256 + mh * 128 + row) * 64 + q * 4);
                }
                if (half == 0 && mh > 0) __syncthreads();
#pragma unroll
                for (int i = 0; i < 4; i++) {
                    int idx = tid + (half * 4 + i) * 256;
                    int row = idx >> 4, q = idx & 15;
                    uint2 hi, lo; split_f4(tmp[i], hi, lo);
                    uint32_t off = SWZ((uint32_t)(row * 128 + q * 8));
                    *(uint2*)(sm + OAH + off) = hi;
                    *(uint2*)(sm + OAL + off) = lo;
                }
            }
        }
        __syncthreads();

        float acc[4][4][4] = {};
        uint32_t bB = sb + OBH + (uint32_t)((wn >> 1) * 8192);
        int pb2 = (wn & 1) * 64;
#pragma unroll
        for (int kk = 0; kk < 4; kk++) {
            uint32_t ah[4][4], al[4][4], bh[4][2], bl[4][2];
#pragma unroll
            for (int mt = 0; mt < 4; mt++) {
                ldmx4(ah[mt], ldm_addr(sb + OAH, wm * 64 + mt * 16, lane, kk * 32));
                ldmx4(al[mt], ldm_addr(sb + OAL, wm * 64 + mt * 16, lane, kk * 32));
            }
#pragma unroll
            for (int bt = 0; bt < 2; bt++) {
                uint32_t r[4];
                ldmx4t(r, ldm_addr(bB, kk * 16, lane, pb2 + bt * 32));
                bh[bt*2][0] = r[0]; bh[bt*2][1] = r[1];
                bh[bt*2+1][0] = r[2]; bh[bt*2+1][1] = r[3];
                ldmx4t(r, ldm_addr(bB + 16384, kk * 16, lane, pb2 + bt * 32));
                bl[bt*2][0] = r[0]; bl[bt*2][1] = r[1];
                bl[bt*2+1][0] = r[2]; bl[bt*2+1][1] = r[3];
            }
#pragma unroll
            for (int mt = 0; mt < 4; mt++)
#pragma unroll
                for (int nt = 0; nt < 4; nt++) {
                    mma16816(acc[mt][nt], ah[mt], bh[nt]);
                    mma16816(acc[mt][nt], ah[mt], bl[nt]);
                    mma16816(acc[mt][nt], al[mt], bh[nt]);
                }
        }
#pragma unroll
        for (int mt = 0; mt < 4; mt++) {
            int ca = wm * 64 + mt * 16 + g;
            size_t ra = (size_t)(b * 256 + mh * 128 + ca) * Nn + n0;
            size_t rb = ra + (size_t)8 * Nn;
#pragma unroll
            for (int nt = 0; nt < 4; nt++) {
                int px = wn * 32 + nt * 8 + tig * 2;
                float2 xa = ldcs2(x + ra + px);
                float2 xb = ldcs2(x + rb + px);
                stcs2(out + ra + px, make_float2(acc[mt][nt][0] + xa.x, acc[mt][nt][1] + xa.y));
                stcs2(out + rb + px, make_float2(acc[mt][nt][2] + xb.x, acc[mt][nt][3] + xb.y));
            }
        }
    }
}

// ---------------- launcher ----------------
extern "C" void kernel_launch(void* const* d_in, const int* in_sizes, int n_in,
                              void* d_out, int out_size) {
    const float* x      = (const float*)d_in[0];
    const float* ln_w   = (const float*)d_in[1];
    const float* ln_b   = (const float*)d_in[2];
    const float* w_bcdt = (const float*)d_in[3];
    const float* w_gw   = (const float*)d_in[4];
    const float* w_out  = (const float*)d_in[5];
    const float* A      = (const float*)d_in[6];
    float* out = (float*)d_out;

    cudaFuncSetAttribute(gemm1_mma, cudaFuncAttributeMaxDynamicSharedMemorySize, 65536);
    cudaFuncSetAttribute(hgemm_mma, cudaFuncAttributeMaxDynamicSharedMemorySize, 49152);
    cudaFuncSetAttribute(final_mma, cudaFuncAttributeMaxDynamicSharedMemorySize, 65536);

    prep_w_k<<<128, 256>>>(w_bcdt, ln_w, ln_b);
    gemm1_mma<<<dim3(32, Bsz), 256, 65536>>>(x);
    conv_k<<<dim3(2, 32, Bsz), 256>>>(w_gw);
    softmax_k<<<dim3(S, Bsz), 256>>>(A);
    hgemm_mma<<<dim3(KSPLIT, 2, Bsz), 256, 49152>>>(x);
    h2_k<<<dim3(C / 64, Bsz), 256>>>(w_out);
    final_mma<<<dim3(32, Bsz), 256, 65536>>>(x, out);
}

// round 17
// speedup vs baseline: 1.1184x; 1.1184x over previous
#include <cuda_runtime.h>
#include <cuda_bf16.h>
#include <cstdint>

static constexpr int Bsz = 32;
static constexpr int C   = 256;
static constexpr int Nn  = 4096;
static constexpr int S   = 64;
static constexpr int CD  = 128;
static constexpr float EPS = 1e-5f;
static constexpr int KSPLIT = 4;

// ---------------- scratch ----------------
__device__ float g_rowsum[CD];
__device__ float g_bias  [CD];
__device__ __nv_bfloat16 g_wp_hi[CD * C], g_wp_lo[CD * C];
__device__ float g_bcdt[(size_t)Bsz * CD * Nn];
__device__ float g_cv  [(size_t)Bsz * CD * Nn];
__device__ __nv_bfloat16 g_ab_hi[(size_t)Bsz * S * Nn], g_ab_lo[(size_t)Bsz * S * Nn];
__device__ float g_hpart[(size_t)KSPLIT * Bsz * C * S];
__device__ float g_h2  [(size_t)Bsz * C * S];

// ---------------- helpers ----------------
#define SWZ(o)   ((o) ^ (((o) >> 3) & 0x70))
#define SWZ64(o) ((o) ^ (((o) >> 3) & 0x30))

__device__ __forceinline__ uint32_t smem_u32(const void* p) {
    uint32_t a;
    asm("{ .reg .u64 t; cvta.to.shared.u64 t, %1; cvt.u32.u64 %0, t; }" : "=r"(a) : "l"(p));
    return a;
}
__device__ __forceinline__ void ldmx4(uint32_t* r, uint32_t addr) {
    asm volatile("ldmatrix.sync.aligned.m8n8.x4.shared.b16 {%0,%1,%2,%3}, [%4];"
        : "=r"(r[0]), "=r"(r[1]), "=r"(r[2]), "=r"(r[3]) : "r"(addr));
}
__device__ __forceinline__ void ldmx4t(uint32_t* r, uint32_t addr) {
    asm volatile("ldmatrix.sync.aligned.m8n8.x4.trans.shared.b16 {%0,%1,%2,%3}, [%4];"
        : "=r"(r[0]), "=r"(r[1]), "=r"(r[2]), "=r"(r[3]) : "r"(addr));
}
__device__ __forceinline__ void mma16816(float* d, const uint32_t* a, const uint32_t* b) {
    asm volatile("mma.sync.aligned.m16n8k16.row.col.f32.bf16.bf16.f32 "
        "{%0,%1,%2,%3}, {%4,%5,%6,%7}, {%8,%9}, {%0,%1,%2,%3};"
        : "+f"(d[0]), "+f"(d[1]), "+f"(d[2]), "+f"(d[3])
        : "r"(a[0]), "r"(a[1]), "r"(a[2]), "r"(a[3]), "r"(b[0]), "r"(b[1]));
}
__device__ __forceinline__ uint32_t ldm_addr(uint32_t base, int rowbase, int lane, int kByte) {
    int o = (rowbase + (lane & 15)) * 128 + kByte + ((lane >> 4) * 16);
    return base + SWZ(o);
}
__device__ __forceinline__ uint32_t ldm_addr64(uint32_t base, int rowbase, int lane, int kByte) {
    int o = (rowbase + (lane & 15)) * 64 + kByte + ((lane >> 4) * 16);
    return base + SWZ64(o);
}
__device__ __forceinline__ void cp16(uint32_t dst, const void* src) {
    asm volatile("cp.async.ca.shared.global [%0], [%1], 16;" :: "r"(dst), "l"(src));
}
#define CP_COMMIT asm volatile("cp.async.commit_group;" ::: "memory")
#define CP_WAIT0  asm volatile("cp.async.wait_group 0;" ::: "memory")

__device__ __forceinline__ void stcs2(float* p, float2 v) {
    asm volatile("st.global.cs.v2.f32 [%0], {%1, %2};" :: "l"(p), "f"(v.x), "f"(v.y) : "memory");
}

__device__ __forceinline__ uint32_t pk(__nv_bfloat16 a, __nv_bfloat16 b) {
    return (uint32_t)__bfloat16_as_ushort(a) | ((uint32_t)__bfloat16_as_ushort(b) << 16);
}
__device__ __forceinline__ void split_sc(float x, __nv_bfloat16& h, __nv_bfloat16& l) {
    h = __float2bfloat16(x);
    l = __float2bfloat16(x - __bfloat162float(h));
}
__device__ __forceinline__ void split_f4(float4 v, uint2& hi, uint2& lo) {
    __nv_bfloat16 hx, hy, hz, hw, lx, ly, lz, lw;
    split_sc(v.x, hx, lx); split_sc(v.y, hy, ly);
    split_sc(v.z, hz, lz); split_sc(v.w, hw, lw);
    hi.x = pk(hx, hy); hi.y = pk(hz, hw);
    lo.x = pk(lx, ly); lo.y = pk(lz, lw);
}

// ---------------- K0: fold LN into proj weights ----------------
__global__ void prep_w_k(const float* __restrict__ w_bcdt,
                         const float* __restrict__ ln_w,
                         const float* __restrict__ ln_b) {
    int o = blockIdx.x, c = threadIdx.x;
    float w  = w_bcdt[o * C + c];
    float wp = w * ln_w[c];
    __nv_bfloat16 h, l; split_sc(wp, h, l);
    g_wp_hi[o * C + c] = h;
    g_wp_lo[o * C + c] = l;
    __shared__ float s1[256], s2[256];
    s1[c] = wp;
    s2[c] = w * ln_b[c];
    __syncthreads();
    for (int st = 128; st > 0; st >>= 1) {
        if (c < st) { s1[c] += s1[c + st]; s2[c] += s2[c + st]; }
        __syncthreads();
    }
    if (c == 0) { g_rowsum[o] = s1[0]; g_bias[o] = s2[0]; }
}

// ---------------- GEMM1: D[cd128][pix128] = Wp * x, K=256 in 8 K=32 panels ----------------
__global__ __launch_bounds__(256, 2) void gemm1_mma(const float* __restrict__ x) {
    extern __shared__ char sm[];
    __shared__ float sm_mean[128], sm_inv[128];
    uint32_t sb = smem_u32(sm);
    const uint32_t OA = 0, OB = 32768;
    int tid = threadIdx.x, wid = tid >> 5, lane = tid & 31;
    int b = blockIdx.y, n0 = blockIdx.x * 128;
    int wm = wid & 1, wn = wid >> 1;
    const float* xg = x + (size_t)b * C * Nn;
    float acc[4][4][4] = {};
    float4 xr[4];
    float sacc[4] = {}, sqacc[4] = {};

    auto issueA = [&](int p, int buf) {
        uint32_t da = sb + OA + buf * 16384;
#pragma unroll
        for (int i = 0; i < 2; i++) {
            int idx = tid + i * 256;
            int cd = idx >> 2, k8 = idx & 3;
            uint32_t off = SWZ64((uint32_t)(cd * 64 + k8 * 16));
            cp16(da + off,        g_wp_hi + cd * 256 + p * 32 + k8 * 8);
            cp16(da + 8192 + off, g_wp_lo + cd * 256 + p * 32 + k8 * 8);
        }
    };
    auto loadX = [&](int p) {
#pragma unroll
        for (int i = 0; i < 4; i++) {
            int idx = tid + i * 256;
            int c = idx >> 5, pix4 = idx & 31;
            float4 v = *(const float4*)(xg + (size_t)(p * 32 + c) * Nn + n0 + pix4 * 4);
            xr[i] = v;
            sacc[0] += v.x; sqacc[0] = fmaf(v.x, v.x, sqacc[0]);
            sacc[1] += v.y; sqacc[1] = fmaf(v.y, v.y, sqacc[1]);
            sacc[2] += v.z; sqacc[2] = fmaf(v.z, v.z, sqacc[2]);
            sacc[3] += v.w; sqacc[3] = fmaf(v.w, v.w, sqacc[3]);
        }
    };
    auto storeX = [&](int buf) {
        char* db = sm + OB + buf * 16384;
#pragma unroll
        for (int i = 0; i < 4; i++) {
            int idx = tid + i * 256;
            int c = idx >> 5, pix4 = idx & 31;
            uint2 hi, lo; split_f4(xr[i], hi, lo);
            uint32_t off = (uint32_t)((pix4 >> 4) * 4096) + SWZ((uint32_t)(c * 128 + (pix4 & 15) * 8));
            *(uint2*)(db + off)        = hi;
            *(uint2*)(db + 8192 + off) = lo;
        }
    };
    auto compute = [&](int buf) {
        uint32_t aB = sb + OA + buf * 16384;
        uint32_t bB = sb + OB + buf * 16384 + (uint32_t)((wn >> 1) * 4096);
        int pb2 = (wn & 1) * 64;
#pragma unroll
        for (int kk = 0; kk < 2; kk++) {
            uint32_t ah[4][4], al[4][4], bh[4][2], bl[4][2];
#pragma unroll
            for (int mt = 0; mt < 4; mt++) {
                ldmx4(ah[mt], ldm_addr64(aB,        wm * 64 + mt * 16, lane, kk * 32));
                ldmx4(al[mt], ldm_addr64(aB + 8192, wm * 64 + mt * 16, lane, kk * 32));
            }
#pragma unroll
            for (int bt = 0; bt < 2; bt++) {
                uint32_t r[4];
                ldmx4t(r, ldm_addr(bB, kk * 16, lane, pb2 + bt * 32));
                bh[bt*2][0] = r[0]; bh[bt*2][1] = r[1];
                bh[bt*2+1][0] = r[2]; bh[bt*2+1][1] = r[3];
                ldmx4t(r, ldm_addr(bB + 8192, kk * 16, lane, pb2 + bt * 32));
                bl[bt*2][0] = r[0]; bl[bt*2][1] = r[1];
                bl[bt*2+1][0] = r[2]; bl[bt*2+1][1] = r[3];
            }
#pragma unroll
            for (int mt = 0; mt < 4; mt++)
#pragma unroll
                for (int nt = 0; nt < 4; nt++) {
                    mma16816(acc[mt][nt], ah[mt], bh[nt]);
                    mma16816(acc[mt][nt], ah[mt], bl[nt]);
                    mma16816(acc[mt][nt], al[mt], bh[nt]);
                }
        }
    };

    issueA(0, 0); loadX(0); storeX(0);
    CP_COMMIT; CP_WAIT0;
    __syncthreads();
    for (int p = 0; p < 8; p++) {
        int buf = p & 1;
        if (p < 7) { issueA(p + 1, buf ^ 1); loadX(p + 1); }
        compute(buf);
        if (p < 7) {
            storeX(buf ^ 1);
            CP_COMMIT; CP_WAIT0;
            __syncthreads();
        }
    }

    // --- fused LN stats ---
    int g = lane >> 2, tig = lane & 3;
    float rs[4][2], bi[4][2];
#pragma unroll
    for (int mt = 0; mt < 4; mt++) {
        int cd0 = wm * 64 + mt * 16 + g;
        rs[mt][0] = g_rowsum[cd0];     bi[mt][0] = g_bias[cd0];
        rs[mt][1] = g_rowsum[cd0 + 8]; bi[mt][1] = g_bias[cd0 + 8];
    }
    __syncthreads();
    float* red = (float*)sm;
    {
        int r8 = tid >> 5, p4 = (tid & 31) * 4;
#pragma unroll
        for (int j = 0; j < 4; j++) {
            red[r8 * 128 + p4 + j]        = sacc[j];
            red[1024 + r8 * 128 + p4 + j] = sqacc[j];
        }
    }
    __syncthreads();
    if (tid < 128) {
        float s = 0.f, q = 0.f;
#pragma unroll
        for (int r = 0; r < 8; r++) {
            s += red[r * 128 + tid];
            q += red[1024 + r * 128 + tid];
        }
        float m = s * (1.f / 256.f);
        float var = (q - 256.f * m * m) * (1.f / 255.f);
        sm_mean[tid] = m;
        sm_inv[tid]  = rsqrtf(var + EPS);
    }
    __syncthreads();

    float* outp = g_bcdt + (size_t)b * CD * Nn + n0;
    float me[4][2], iv[4][2];
    int px[4];
#pragma unroll
    for (int nt = 0; nt < 4; nt++) {
        px[nt] = wn * 32 + nt * 8 + tig * 2;
        me[nt][0] = sm_mean[px[nt]];     iv[nt][0] = sm_inv[px[nt]];
        me[nt][1] = sm_mean[px[nt] + 1]; iv[nt][1] = sm_inv[px[nt] + 1];
    }
#pragma unroll
    for (int mt = 0; mt < 4; mt++) {
        int cd0 = wm * 64 + mt * 16 + g, cd1 = cd0 + 8;
#pragma unroll
        for (int nt = 0; nt < 4; nt++) {
            float2 v0 = make_float2(
                iv[nt][0] * (acc[mt][nt][0] - me[nt][0] * rs[mt][0]) + bi[mt][0],
                iv[nt][1] * (acc[mt][nt][1] - me[nt][1] * rs[mt][0]) + bi[mt][0]);
            float2 v1 = make_float2(
                iv[nt][0] * (acc[mt][nt][2] - me[nt][0] * rs[mt][1]) + bi[mt][1],
                iv[nt][1] * (acc[mt][nt][3] - me[nt][1] * rs[mt][1]) + bi[mt][1]);
            *(float2*)(outp + (size_t)cd0 * Nn + px[nt]) = v0;
            *(float2*)(outp + (size_t)cd1 * Nn + px[nt]) = v1;
        }
    }
}

// ---------------- grouped 3x3 conv ----------------
__global__ __launch_bounds__(256) void conv_k(const float* __restrict__ w_gw) {
    __shared__ float si[4][34][72];
    __shared__ float sw[4][4][9];
    int b = blockIdx.z, g = blockIdx.y, ys = blockIdx.x;
    int tid = threadIdx.x;
    if (tid < 144) {
        int o = tid / 36, r = tid % 36;
        sw[o][r / 9][r % 9] = w_gw[(g * 4 + o) * 36 + r];
    }
    const float* inp = g_bcdt + ((size_t)(b * CD + g * 4)) * Nn;
    int y0 = ys * 32;
    if (tid < 136) {
        int ch = tid / 34, row = tid % 34;
        si[ch][row][3]  = 0.f;
        si[ch][row][68] = 0.f;
    }
#pragma unroll
    for (int ch = 0; ch < 4; ch++) {
        for (int j = tid; j < 34 * 16; j += 256) {
            int row = j >> 4, c4 = (j & 15) * 4;
            int gy = y0 - 1 + row;
            float4 v = make_float4(0.f, 0.f, 0.f, 0.f);
            if ((unsigned)gy < 64u) v = *(const float4*)(inp + ch * Nn + gy * 64 + c4);
            *(float4*)(&si[ch][row][4 + c4]) = v;
        }
    }
    __syncthreads();
    int ly = tid >> 3, lx8 = (tid & 7) * 8;
    float acc[4][8] = {};
#pragma unroll
    for (int ch = 0; ch < 4; ch++)
#pragma unroll
        for (int ky = 0; ky < 3; ky++) {
            float r[10];
#pragma unroll
            for (int j = 0; j < 10; j++) r[j] = si[ch][ly + ky][3 + lx8 + j];
#pragma unroll
            for (int o = 0; o < 4; o++) {
                float w0 = sw[o][ch][ky*3], w1 = sw[o][ch][ky*3+1], w2 = sw[o][ch][ky*3+2];
#pragma unroll
                for (int p = 0; p < 8; p++)
                    acc[o][p] = fmaf(r[p], w0, fmaf(r[p+1], w1, fmaf(r[p+2], w2, acc[o][p])));
            }
        }
    float* op = g_cv + ((size_t)(b * CD + g * 4)) * Nn + (y0 + ly) * 64 + lx8;
#pragma unroll
    for (int o = 0; o < 4; o++) {
        *(float4*)(op + (size_t)o * Nn)     = make_float4(acc[o][0], acc[o][1], acc[o][2], acc[o][3]);
        *(float4*)(op + (size_t)o * Nn + 4) = make_float4(acc[o][4], acc[o][5], acc[o][6], acc[o][7]);
    }
}

// ---------------- softmax + AB -> bf16 planes; float4 I/O ----------------
__global__ __launch_bounds__(256) void softmax_k(const float* __restrict__ A) {
    __shared__ float shm[8], shs[8];
    int b = blockIdx.y, s = blockIdx.x;
    const float4* dt4 = (const float4*)(g_cv + ((size_t)b * CD + S + s) * Nn);
    const float4* bc4 = (const float4*)(g_cv + ((size_t)b * CD + s) * Nn);
    size_t obase = ((size_t)b * S + s) * Nn;
    int tid = threadIdx.x;
    float a = A[s];
    float v[16];
    float mx = -1e30f;
#pragma unroll
    for (int i = 0; i < 4; i++) {
        float4 d = dt4[i * 256 + tid];
        v[i*4+0] = d.x + a; v[i*4+1] = d.y + a;
        v[i*4+2] = d.z + a; v[i*4+3] = d.w + a;
        mx = fmaxf(mx, fmaxf(fmaxf(v[i*4+0], v[i*4+1]), fmaxf(v[i*4+2], v[i*4+3])));
    }
#pragma unroll
    for (int o = 16; o; o >>= 1) mx = fmaxf(mx, __shfl_xor_sync(0xffffffffu, mx, o));
    if ((tid & 31) == 0) shm[tid >> 5] = mx;
    __syncthreads();
    if (tid == 0) {
        float m = shm[0];
        for (int i = 1; i < 8; i++) m = fmaxf(m, shm[i]);
        shm[0] = m;
    }
    __syncthreads();
    mx = shm[0];
    float sum = 0.f;
#pragma unroll
    for (int i = 0; i < 16; i++) { v[i] = __expf(v[i] - mx); sum += v[i]; }
#pragma unroll
    for (int o = 16; o; o >>= 1) sum += __shfl_xor_sync(0xffffffffu, sum, o);
    if ((tid & 31) == 0) shs[tid >> 5] = sum;
    __syncthreads();
    if (tid == 0) {
        float m = 0.f;
        for (int i = 0; i < 8; i++) m += shs[i];
        shs[0] = m;
    }
    __syncthreads();
    float invs = 1.f / shs[0];
    uint2* abh = (uint2*)(g_ab_hi + obase);
    uint2* abl = (uint2*)(g_ab_lo + obase);
#pragma unroll
    for (int i = 0; i < 4; i++) {
        float4 bc = bc4[i * 256 + tid];
        float4 val = make_float4(v[i*4+0] * invs * bc.x, v[i*4+1] * invs * bc.y,
                                 v[i*4+2] * invs * bc.z, v[i*4+3] * invs * bc.w);
        uint2 hi, lo; split_f4(val, hi, lo);
        abh[i * 256 + tid] = hi;
        abl[i * 256 + tid] = lo;
    }
}

// ---------------- hgemm: K=32 panels, double buffered; split-K=4 ----------------
__global__ __launch_bounds__(256, 2) void hgemm_mma(const float* __restrict__ x) {
    extern __shared__ char sm[];
    uint32_t sb = smem_u32(sm);
    int tid = threadIdx.x, wid = tid >> 5, lane = tid & 31;
    int ks = blockIdx.x, mh = blockIdx.y, b = blockIdx.z;
    int wm = wid & 3, wn = wid >> 2;
    float acc[2][4][4] = {};
    const float* xg = x + (size_t)(b * 256 + mh * 128) * Nn + ks * 1024;
    size_t bbase = (size_t)(b * 64) * Nn + ks * 1024;
    float4 ar[4];

    auto issueB = [&](int p, int buf) {
        uint32_t base = sb + buf * 24576;
        int row = tid >> 2, k8 = tid & 3;
        uint32_t off = SWZ64((uint32_t)(row * 64 + k8 * 16));
        size_t src = bbase + (size_t)row * Nn + p * 32 + k8 * 8;
        cp16(base + 16384 + off, g_ab_hi + src);
        cp16(base + 20480 + off, g_ab_lo + src);
    };
    auto loadA = [&](int p) {
#pragma unroll
        for (int i = 0; i < 4; i++) {
            int idx = tid + i * 256;
            int row = idx >> 3, q = idx & 7;
            ar[i] = *(const float4*)(xg + (size_t)row * Nn + p * 32 + q * 4);
        }
    };
    auto storeA = [&](int buf) {
        char* da = sm + buf * 24576;
#pragma unroll
        for (int i = 0; i < 4; i++) {
            int idx = tid + i * 256;
            int row = idx >> 3, q = idx & 7;
            uint2 hi, lo; split_f4(ar[i], hi, lo);
            uint32_t off = SWZ64((uint32_t)(row * 64 + q * 8));
            *(uint2*)(da + off)        = hi;
            *(uint2*)(da + 8192 + off) = lo;
        }
    };
    auto compute = [&](int buf) {
        uint32_t aB = sb + buf * 24576;
        uint32_t bB = aB + 16384;
#pragma unroll
        for (int kk = 0; kk < 2; kk++) {
            uint32_t ah[2][4], al[2][4], bh[4][2], bl[4][2];
#pragma unroll
            for (int mt = 0; mt < 2; mt++) {
                ldmx4(ah[mt], ldm_addr64(aB,        wm * 32 + mt * 16, lane, kk * 32));
                ldmx4(al[mt], ldm_addr64(aB + 8192, wm * 32 + mt * 16, lane, kk * 32));
            }
#pragma unroll
            for (int bt = 0; bt < 2; bt++) {
                uint32_t r[4];
                ldmx4(r, ldm_addr64(bB, wn * 32 + bt * 16, lane, kk * 32));
                bh[bt*2][0] = r[0]; bh[bt*2][1] = r[2];
                bh[bt*2+1][0] = r[1]; bh[bt*2+1][1] = r[3];
                ldmx4(r, ldm_addr64(bB + 4096, wn * 32 + bt * 16, lane, kk * 32));
                bl[bt*2][0] = r[0]; bl[bt*2][1] = r[2];
                bl[bt*2+1][0] = r[1]; bl[bt*2+1][1] = r[3];
            }
#pragma unroll
            for (int mt = 0; mt < 2; mt++)
#pragma unroll
                for (int nt = 0; nt < 4; nt++) {
                    mma16816(acc[mt][nt], ah[mt], bh[nt]);
                    mma16816(acc[mt][nt], ah[mt], bl[nt]);
                    mma16816(acc[mt][nt], al[mt], bh[nt]);
                }
        }
    };

    issueB(0, 0); loadA(0); storeA(0);
    CP_COMMIT; CP_WAIT0;
    __syncthreads();
    for (int p = 0; p < 32; p++) {
        int buf = p & 1;
        if (p < 31) { issueB(p + 1, buf ^ 1); loadA(p + 1); }
        compute(buf);
        if (p < 31) {
            storeA(buf ^ 1);
            CP_COMMIT; CP_WAIT0;
            __syncthreads();
        }
    }

    int g = lane >> 2, tig = lane & 3;
    float* hp = g_hpart + (size_t)ks * (Bsz * C * S) + (size_t)(b * 256 + mh * 128) * 64;
#pragma unroll
    for (int mt = 0; mt < 2; mt++) {
        int ca = wm * 32 + mt * 16 + g;
#pragma unroll
        for (int nt = 0; nt < 4; nt++) {
            int s0 = wn * 32 + nt * 8 + tig * 2;
            *(float2*)(hp + (size_t)ca * 64 + s0)       = make_float2(acc[mt][nt][0], acc[mt][nt][1]);
            *(float2*)(hp + (size_t)(ca + 8) * 64 + s0) = make_float2(acc[mt][nt][2], acc[mt][nt][3]);
        }
    }
}

// ---------------- h2 = w_out @ h; fused split-K reduce ----------------
__global__ __launch_bounds__(256) void h2_k(const float* __restrict__ w_out) {
    __shared__ float ws[16][65];
    __shared__ float hs[16][68];
    int m0 = blockIdx.x * 64, b = blockIdx.y;
    int tid = threadIdx.x;
    int tm = tid >> 4, tn = tid & 15;
    float acc[4][4] = {};
    int lm = tid >> 2, lk4 = (tid & 3) * 4;
    int hk = tid >> 4, hs4 = (tid & 15) * 4;
    const size_t PSTRIDE = (size_t)Bsz * C * S;
    for (int k0 = 0; k0 < C; k0 += 16) {
        float4 wv = *(const float4*)(w_out + (size_t)(m0 + lm) * C + k0 + lk4);
        size_t hoff = (size_t)(b * C + k0 + hk) * S + hs4;
        float4 hv = make_float4(0.f, 0.f, 0.f, 0.f);
#pragma unroll
        for (int p = 0; p < KSPLIT; p++) {
            float4 t = *(const float4*)(g_hpart + p * PSTRIDE + hoff);
            hv.x += t.x; hv.y += t.y; hv.z += t.z; hv.w += t.w;
        }
        __syncthreads();
        ws[lk4 + 0][lm] = wv.x; ws[lk4 + 1][lm] = wv.y;
        ws[lk4 + 2][lm] = wv.z; ws[lk4 + 3][lm] = wv.w;
        hs[hk][hs4 + 0] = hv.x; hs[hk][hs4 + 1] = hv.y;
        hs[hk][hs4 + 2] = hv.z; hs[hk][hs4 + 3] = hv.w;
        __syncthreads();
#pragma unroll
        for (int k = 0; k < 16; k++) {
            float a[4], bb[4];
#pragma unroll
            for (int i = 0; i < 4; i++) a[i] = ws[k][tm * 4 + i];
#pragma unroll
            for (int j = 0; j < 4; j++) bb[j] = hs[k][tn * 4 + j];
#pragma unroll
            for (int i = 0; i < 4; i++)
#pragma unroll
                for (int j = 0; j < 4; j++) acc[i][j] = fmaf(a[i], bb[j], acc[i][j]);
        }
    }
    float* o = g_h2 + ((size_t)b * C + m0) * S;
#pragma unroll
    for (int i = 0; i < 4; i++)
#pragma unroll
        for (int j = 0; j < 4; j++)
            o[(size_t)(tm * 4 + i) * S + tn * 4 + j] = acc[i][j];
}

// ---------------- final: out[c256][pix128] = h2 @ BC + x; mh fused; streaming out ----------------
__global__ __launch_bounds__(256, 2) void final_mma(const float* __restrict__ x,
                                                    float* __restrict__ out) {
    extern __shared__ char sm[];
    uint32_t sb = smem_u32(sm);
    const uint32_t OAH = 0, OAL = 16384, OBH = 32768, OBL = 49152;
    int tid = threadIdx.x, wid = tid >> 5, lane = tid & 31;
    int n0 = blockIdx.x * 128, b = blockIdx.y;
    int wm = wid & 1, wn = wid >> 1;
    int g = lane >> 2, tig = lane & 3;

#pragma unroll
    for (int half = 0; half < 2; half++) {
        float4 tmp[4];
#pragma unroll
        for (int i = 0; i < 4; i++) {
            int idx = tid + (half * 4 + i) * 256;
            int s = idx >> 5, pix4 = idx & 31;
            tmp[i] = *(const float4*)(g_cv + (size_t)(b * CD + s) * Nn + n0 + pix4 * 4);
        }
#pragma unroll
        for (int i = 0; i < 4; i++) {
            int idx = tid + (half * 4 + i) * 256;
            int s = idx >> 5, pix4 = idx & 31;
            uint2 hi, lo; split_f4(tmp[i], hi, lo);
            uint32_t off = (uint32_t)((pix4 >> 4) * 8192) + SWZ((uint32_t)(s * 128 + (pix4 & 15) * 8));
            *(uint2*)(sm + OBH + off) = hi;
            *(uint2*)(sm + OBL + off) = lo;
        }
    }

    for (int mh = 0; mh < 2; mh++) {
        {
            float4 tmp[4];
#pragma unroll
            for (int half = 0; half < 2; half++) {
#pragma unroll
                for (int i = 0; i < 4; i++) {
                    int idx = tid + (half * 4 + i) * 256;
                    int row = idx >> 4, q = idx & 15;
                    tmp[i] = *(const float4*)(g_h2 + (size_t)(b * 256 + mh * 128 + row) * 64 + q * 4);
                }
                if (half == 0 && mh > 0) __syncthreads();
#pragma unroll
                for (int i = 0; i < 4; i++) {
                    int idx = tid + (half * 4 + i) * 256;
                    int row = idx >> 4, q = idx & 15;
                    uint2 hi, lo; split_f4(tmp[i], hi, lo);
                    uint32_t off = SWZ((uint32_t)(row * 128 + q * 8));
                    *(uint2*)(sm + OAH + off) = hi;
                    *(uint2*)(sm + OAL + off) = lo;
                }
            }
        }
        __syncthreads();

        float acc[4][4][4] = {};
        uint32_t bB = sb + OBH + (uint32_t)((wn >> 1) * 8192);
        int pb2 = (wn & 1) * 64;
#pragma unroll
        for (int kk = 0; kk < 4; kk++) {
            uint32_t ah[4][4], al[4][4], bh[4][2], bl[4][2];
#pragma unroll
            for (int mt = 0; mt < 4; mt++) {
                ldmx4(ah[mt], ldm_addr(sb + OAH, wm * 64 + mt * 16, lane, kk * 32));
                ldmx4(al[mt], ldm_addr(sb + OAL, wm * 64 + mt * 16, lane, kk * 32));
            }
#pragma unroll
            for (int bt = 0; bt < 2; bt++) {
                uint32_t r[4];
                ldmx4t(r, ldm_addr(bB, kk * 16, lane, pb2 + bt * 32));
                bh[bt*2][0] = r[0]; bh[bt*2][1] = r[1];
                bh[bt*2+1][0] = r[2]; bh[bt*2+1][1] = r[3];
                ldmx4t(r, ldm_addr(bB + 16384, kk * 16, lane, pb2 + bt * 32));
                bl[bt*2][0] = r[0]; bl[bt*2][1] = r[1];
                bl[bt*2+1][0] = r[2]; bl[bt*2+1][1] = r[3];
            }
#pragma unroll
            for (int mt = 0; mt < 4; mt++)
#pragma unroll
                for (int nt = 0; nt < 4; nt++) {
                    mma16816(acc[mt][nt], ah[mt], bh[nt]);
                    mma16816(acc[mt][nt], ah[mt], bl[nt]);
                    mma16816(acc[mt][nt], al[mt], bh[nt]);
                }
        }
#pragma unroll
        for (int mt = 0; mt < 4; mt++) {
            int ca = wm * 64 + mt * 16 + g;
            size_t ra = (size_t)(b * 256 + mh * 128 + ca) * Nn + n0;
            size_t rb = ra + (size_t)8 * Nn;
#pragma unroll
            for (int nt = 0; nt < 4; nt++) {
                int px = wn * 32 + nt * 8 + tig * 2;
                float2 xa = *(const float2*)(x + ra + px);
                float2 xb = *(const float2*)(x + rb + px);
                stcs2(out + ra + px, make_float2(acc[mt][nt][0] + xa.x, acc[mt][nt][1] + xa.y));
                stcs2(out + rb + px, make_float2(acc[mt][nt][2] + xb.x, acc[mt][nt][3] + xb.y));
            }
        }
    }
}

// ---------------- launcher ----------------
extern "C" void kernel_launch(void* const* d_in, const int* in_sizes, int n_in,
                              void* d_out, int out_size) {
    const float* x      = (const float*)d_in[0];
    const float* ln_w   = (const float*)d_in[1];
    const float* ln_b   = (const float*)d_in[2];
    const float* w_bcdt = (const float*)d_in[3];
    const float* w_gw   = (const float*)d_in[4];
    const float* w_out  = (const float*)d_in[5];
    const float* A      = (const float*)d_in[6];
    float* out = (float*)d_out;

    cudaFuncSetAttribute(gemm1_mma, cudaFuncAttributeMaxDynamicSharedMemorySize, 65536);
    cudaFuncSetAttribute(hgemm_mma, cudaFuncAttributeMaxDynamicSharedMemorySize, 49152);
    cudaFuncSetAttribute(final_mma, cudaFuncAttributeMaxDynamicSharedMemorySize, 65536);

    prep_w_k<<<128, 256>>>(w_bcdt, ln_w, ln_b);
    gemm1_mma<<<dim3(32, Bsz), 256, 65536>>>(x);
    conv_k<<<dim3(2, 32, Bsz), 256>>>(w_gw);
    softmax_k<<<dim3(S, Bsz), 256>>>(A);
    hgemm_mma<<<dim3(KSPLIT, 2, Bsz), 256, 49152>>>(x);
    h2_k<<<dim3(C / 64, Bsz), 256>>>(w_out);
    final_mma<<<dim3(32, Bsz), 256, 65536>>>(x, out);
}